// round 13
// baseline (speedup 1.0000x reference)
#include <cuda_runtime.h>
#include <cstdint>

// Problem constants (from reference)
#define F 8
#define B 4096
#define V 100000
#define D 128
#define NVALS 81920
#define CHUNK 32
#define CPF (NVALS / CHUNK)   // 2560 chunks per feature (divisible by WPB)
#define STAGES 7              // per-warp smem pipeline depth (rows in flight)
#define WPB 8                 // warps per block
#define TPB (WPB * 32)        // 256 threads

template<int N>
__device__ __forceinline__ void cp_wait() {
    asm volatile("cp.async.wait_group %0;" :: "n"(N) : "memory");
}

// One warp per 32-value chunk (perfectly balanced). Row gathers staged through
// a per-warp 7-deep SMEM ring via cp.async. Segment lookup: the block loads
// the ENTIRE per-feature offsets array (4097 ints, 16KB) into smem with
// coalesced loads (~129 L1 transactions), one __syncthreads, then every
// thread runs an exact 12-step binary search purely in LDS — no dependent
// global chain, no barrier shadow, no windowing edge cases. Partial bag sums
// flushed with red.global.add.v4.f32 (output pre-zeroed by the memset node).
__global__ __launch_bounds__(TPB)
void ebc_chunk_kernel(const int* __restrict__ values,    // [F, NVALS]
                      const int* __restrict__ offsets,   // [F, B+1]
                      const float* __restrict__ tables,  // [F, V, D]
                      float* __restrict__ out)           // [B, F*D]
{
    __shared__ float4 sbuf[WPB][STAGES][32];   // 28 KB gather ring
    __shared__ int soffs[B + 1];               // 16.4 KB: full offsets row

    const int wib   = threadIdx.x >> 5;
    const int lane  = threadIdx.x & 31;
    const int gwarp = blockIdx.x * WPB + wib;

    // f-major: all warps of a block share one feature/table (L2 locality)
    const int f = gwarp / CPF;
    const int c = gwarp - f * CPF;
    const int pos = c * CHUNK + lane;          // this lane's value position

    const int myidx = __ldg(values + (size_t)f * NVALS + pos);

    const float4* tab = reinterpret_cast<const float4*>(tables)
                        + (size_t)f * V * (D / 4) + lane;

    const uint32_t sbase =
        (uint32_t)__cvta_generic_to_shared(&sbuf[wib][0][lane]);

    // issue row r's 512B gather into stage r % STAGES (one 16B cp.async/lane)
    auto issue = [&](int r) {
        const int row = __shfl_sync(0xffffffffu, myidx, r);
        const float4* src = tab + (size_t)row * (D / 4);
        const uint32_t dst = sbase + (uint32_t)((r % STAGES) * 32) * 16u;
        asm volatile("cp.async.cg.shared.global [%0], [%1], 16;\n\t"
                     "cp.async.commit_group;"
                     :: "r"(dst), "l"(src) : "memory");
    };

    // prologue: fill the ring FIRST; the segment lookup hides under it
    #pragma unroll
    for (int r = 0; r < STAGES; ++r) issue(r);

    // ---- segment lookup: whole offsets row in smem ----
    const int* offs = offsets + f * (B + 1);
    #pragma unroll 1
    for (int i = threadIdx.x; i <= B; i += TPB)   // 17 coalesced rounds
        soffs[i] = __ldg(offs + i);
    __syncthreads();

    // myseg = largest j in [0, B-1] with soffs[j] <= pos (12-step LDS bsearch)
    int myseg;
    {
        int lo = 0, hi = B - 1;
        #pragma unroll
        for (int it = 0; it < 12; ++it) {      // 2^12 = 4096 covers [0, B-1]
            int mid = (lo + hi + 1) >> 1;
            if (soffs[mid] <= pos) lo = mid; else hi = mid - 1;
        }
        myseg = lo;
    }
    // ---- end segment lookup ----

    float4 acc = make_float4(0.f, 0.f, 0.f, 0.f);
    int cur = __shfl_sync(0xffffffffu, myseg, 0);

    auto consume = [&](int j) {
        const float4 v = sbuf[wib][j % STAGES][lane];
        const int s = __shfl_sync(0xffffffffu, myseg, j);
        if (s != cur) {                        // warp-uniform branch
            float* o = out + (size_t)cur * (F * D) + f * D + lane * 4;
            asm volatile("red.global.add.v4.f32 [%0], {%1,%2,%3,%4};"
                         :: "l"(o), "f"(acc.x), "f"(acc.y), "f"(acc.z), "f"(acc.w)
                         : "memory");
            acc = make_float4(0.f, 0.f, 0.f, 0.f);
            cur = s;
        }
        acc.x += v.x; acc.y += v.y; acc.z += v.z; acc.w += v.w;
    };

    // steady state: wait oldest, consume, refill
    #pragma unroll
    for (int j = 0; j < CHUNK - STAGES; ++j) {
        cp_wait<STAGES - 1>();
        consume(j);
        issue(j + STAGES);
    }
    // tail: everything issued; drain
    cp_wait<0>();
    #pragma unroll
    for (int j = CHUNK - STAGES; j < CHUNK; ++j) consume(j);

    // final flush
    float* o = out + (size_t)cur * (F * D) + f * D + lane * 4;
    asm volatile("red.global.add.v4.f32 [%0], {%1,%2,%3,%4};"
                 :: "l"(o), "f"(acc.x), "f"(acc.y), "f"(acc.z), "f"(acc.w)
                 : "memory");
}

extern "C" void kernel_launch(void* const* d_in, const int* in_sizes, int n_in,
                              void* d_out, int out_size)
{
    const int*   values  = (const int*)d_in[0];   // [F, NVALS] int32
    const int*   offsets = (const int*)d_in[1];   // [F, B+1] int32
    const float* tables  = (const float*)d_in[2]; // [F, V, D] float32
    float*       out     = (float*)d_out;         // [B, F*D] float32

    // 1) zero the output with a CE memset node (atomics accumulate into it)
    cudaMemsetAsync(out, 0, (size_t)B * F * D * sizeof(float), 0);

    // 2) balanced, smem-pipelined gather + segment-reduce
    const int total_warps = F * CPF;               // 20480
    const int blocks = total_warps / WPB;          // 2560
    ebc_chunk_kernel<<<blocks, TPB>>>(values, offsets, tables, out);
}

// round 14
// speedup vs baseline: 1.2359x; 1.2359x over previous
#include <cuda_runtime.h>
#include <cstdint>

// Problem constants (from reference)
#define F 8
#define B 4096
#define V 100000
#define D 128
#define NVALS 81920
#define CHUNK 32
#define CPF (NVALS / CHUNK)   // 2560 chunks per feature (divisible by WPB)
#define STAGES 8              // per-warp smem pipeline depth (rows in flight)
#define WPB 8                 // warps per block
#define TPB (WPB * 32)        // 256 threads: block covers 256 consecutive positions

template<int N>
__device__ __forceinline__ void cp_wait() {
    asm volatile("cp.async.wait_group %0;" :: "n"(N) : "memory");
}

// One warp per 32-value chunk (perfectly balanced). Row gathers staged through
// a per-warp 8-deep SMEM ring via cp.async. Bag ids computed block-
// cooperatively: warp 0 finds the block's starting segment s0 with a 3-level
// warp-parallel 32-ary search (3 dependent loads instead of 12 -> ~150cyc
// chain, minimal barrier shadow), then one coalesced 257-boundary load into
// smem + per-thread 9-iter LDS upper_bound (INT_MAX sentinel keeps converged
// iterations stable). Partial bag sums flushed with red.global.add.v4.f32
// (output pre-zeroed by the memset node).
__global__ __launch_bounds__(TPB)
void ebc_chunk_kernel(const int* __restrict__ values,    // [F, NVALS]
                      const int* __restrict__ offsets,   // [F, B+1]
                      const float* __restrict__ tables,  // [F, V, D]
                      float* __restrict__ out)           // [B, F*D]
{
    __shared__ float4 sbuf[WPB][STAGES][32];   // 32 KB gather ring
    __shared__ int sb[TPB + 1];                // boundaries offs[s0+1..s0+256] + sentinel
    __shared__ int s_s0;

    const int wib   = threadIdx.x >> 5;
    const int lane  = threadIdx.x & 31;
    const int gwarp = blockIdx.x * WPB + wib;

    // f-major: all warps of a block share one feature/table (L2 locality)
    const int f = gwarp / CPF;
    const int c = gwarp - f * CPF;
    const int pos = c * CHUNK + lane;          // this lane's value position

    const int myidx = __ldg(values + (size_t)f * NVALS + pos);

    const float4* tab = reinterpret_cast<const float4*>(tables)
                        + (size_t)f * V * (D / 4) + lane;

    const uint32_t sbase =
        (uint32_t)__cvta_generic_to_shared(&sbuf[wib][0][lane]);

    // issue row r's 512B gather into stage r % STAGES (one 16B cp.async/lane)
    auto issue = [&](int r) {
        const int row = __shfl_sync(0xffffffffu, myidx, r);
        const float4* src = tab + (size_t)row * (D / 4);
        const uint32_t dst = sbase + (uint32_t)((r & (STAGES - 1)) * 32) * 16u;
        asm volatile("cp.async.cg.shared.global [%0], [%1], 16;\n\t"
                     "cp.async.commit_group;"
                     :: "r"(dst), "l"(src) : "memory");
    };

    // prologue: fill the ring FIRST; the segment lookup hides under it
    #pragma unroll
    for (int r = 0; r < STAGES; ++r) issue(r);

    // ---- block-cooperative segment lookup ----
    const int* offs = offsets + f * (B + 1);
    const int P0 = ((blockIdx.x * WPB) - f * CPF) * CHUNK;  // block's first position

    if (wib == 0) {
        // s0 = largest j in [0, B-1] with offs[j] <= P0, via 3-level 32-ary
        // warp-parallel search (offs[0]=0 <= P0 always -> ballots nonzero).
        unsigned b1 = __ballot_sync(0xffffffffu, __ldg(offs + lane * 128) <= P0);
        int base1 = (31 - __clz(b1)) * 128;                       // 0..3968
        unsigned b2 = __ballot_sync(0xffffffffu, __ldg(offs + base1 + lane * 4) <= P0);
        int base2 = base1 + (31 - __clz(b2)) * 4;                 // 0..4092
        unsigned b3 = __ballot_sync(0xffffffffu, __ldg(offs + base2 + (lane & 3)) <= P0) & 0xFu;
        if (lane == 0) s_s0 = base2 + (31 - __clz(b3));           // 0..4095
    }
    __syncthreads();
    const int s0 = s_s0;

    // coalesced load of the next 256 boundaries (clamped; offs[B]=N > any pos)
    {
        int j = s0 + 1 + threadIdx.x;
        sb[threadIdx.x] = __ldg(offs + (j > B ? B : j));
    }
    if (threadIdx.x == 0) sb[TPB] = 0x7fffffff;   // sentinel
    __syncthreads();

    // cnt = upper_bound(sb[0..255], pos): first index with sb[idx] > pos.
    // Answers in [0,256] (257 values) -> 9 iterations; sentinel keeps
    // post-convergence iterations stable.
    int cnt;
    {
        int lo = 0, hi = TPB;
        #pragma unroll
        for (int it = 0; it < 9; ++it) {
            int mid = (lo + hi) >> 1;
            if (sb[mid] <= pos) lo = mid + 1; else hi = mid;
        }
        cnt = lo;
    }
    int myseg = s0 + cnt;
    if (cnt == TPB) {
        // pathological window (>=256 bags in 256 positions): exact global bsearch
        int lo = 0, hi = B - 1;
        for (int it = 0; it < 12; ++it) {
            int mid = (lo + hi + 1) >> 1;
            if (__ldg(offs + mid) <= pos) lo = mid; else hi = mid - 1;
        }
        myseg = lo;
    }
    // ---- end segment lookup ----

    float4 acc = make_float4(0.f, 0.f, 0.f, 0.f);
    int cur = __shfl_sync(0xffffffffu, myseg, 0);

    auto consume = [&](int j) {
        const float4 v = sbuf[wib][j & (STAGES - 1)][lane];
        const int s = __shfl_sync(0xffffffffu, myseg, j);
        if (s != cur) {                        // warp-uniform branch
            float* o = out + (size_t)cur * (F * D) + f * D + lane * 4;
            asm volatile("red.global.add.v4.f32 [%0], {%1,%2,%3,%4};"
                         :: "l"(o), "f"(acc.x), "f"(acc.y), "f"(acc.z), "f"(acc.w)
                         : "memory");
            acc = make_float4(0.f, 0.f, 0.f, 0.f);
            cur = s;
        }
        acc.x += v.x; acc.y += v.y; acc.z += v.z; acc.w += v.w;
    };

    // steady state: wait oldest, consume, refill
    #pragma unroll
    for (int j = 0; j < CHUNK - STAGES; ++j) {
        cp_wait<STAGES - 1>();
        consume(j);
        issue(j + STAGES);
    }
    // tail: everything issued; drain
    cp_wait<0>();
    #pragma unroll
    for (int j = CHUNK - STAGES; j < CHUNK; ++j) consume(j);

    // final flush
    float* o = out + (size_t)cur * (F * D) + f * D + lane * 4;
    asm volatile("red.global.add.v4.f32 [%0], {%1,%2,%3,%4};"
                 :: "l"(o), "f"(acc.x), "f"(acc.y), "f"(acc.z), "f"(acc.w)
                 : "memory");
}

extern "C" void kernel_launch(void* const* d_in, const int* in_sizes, int n_in,
                              void* d_out, int out_size)
{
    const int*   values  = (const int*)d_in[0];   // [F, NVALS] int32
    const int*   offsets = (const int*)d_in[1];   // [F, B+1] int32
    const float* tables  = (const float*)d_in[2]; // [F, V, D] float32
    float*       out     = (float*)d_out;         // [B, F*D] float32

    // 1) zero the output with a CE memset node (atomics accumulate into it)
    cudaMemsetAsync(out, 0, (size_t)B * F * D * sizeof(float), 0);

    // 2) balanced, smem-pipelined gather + segment-reduce
    const int total_warps = F * CPF;               // 20480
    const int blocks = total_warps / WPB;          // 2560
    ebc_chunk_kernel<<<blocks, TPB>>>(values, offsets, tables, out);
}

// round 15
// speedup vs baseline: 1.2423x; 1.0052x over previous
#include <cuda_runtime.h>
#include <cstdint>

// Problem constants (from reference)
#define F 8
#define B 4096
#define V 100000
#define D 128
#define NVALS 81920
#define CHUNK 32
#define CPF (NVALS / CHUNK)   // 2560 chunks per feature (divisible by WPB)
#define STAGES 8              // per-warp smem pipeline depth (rows in flight)
#define WPB 10                // warps per block (2560 % 10 == 0)
#define TPB (WPB * 32)        // 320 threads: block covers 320 consecutive positions
#define BPF (CPF / WPB)       // 256 blocks per feature

template<int N>
__device__ __forceinline__ void cp_wait() {
    asm volatile("cp.async.wait_group %0;" :: "n"(N) : "memory");
}

// One warp per 32-value chunk (perfectly balanced). Row gathers staged through
// a per-warp 8-deep SMEM ring via cp.async. Bag ids computed block-
// cooperatively: warp 0 finds the block's starting segment s0 with a 3-level
// warp-parallel 32-ary search (3 dependent loads -> ~150cyc chain), then one
// coalesced 321-boundary load into smem + per-thread 9-iter LDS upper_bound
// (INT_MAX sentinel keeps converged iterations stable). Partial bag sums
// flushed with red.global.add.v4.f32 (output pre-zeroed by the memset node).
// WPB=10 -> 5 blocks x 10 warps = 50 warps/SM (was 42): more rows in flight.
__global__ __launch_bounds__(TPB)
void ebc_chunk_kernel(const int* __restrict__ values,    // [F, NVALS]
                      const int* __restrict__ offsets,   // [F, B+1]
                      const float* __restrict__ tables,  // [F, V, D]
                      float* __restrict__ out)           // [B, F*D]
{
    __shared__ float4 sbuf[WPB][STAGES][32];   // 40 KB gather ring
    __shared__ int sb[TPB + 1];                // boundaries offs[s0+1..s0+320] + sentinel
    __shared__ int s_s0;

    const int wib   = threadIdx.x >> 5;
    const int lane  = threadIdx.x & 31;
    const int gwarp = blockIdx.x * WPB + wib;

    // f-major: all warps of a block share one feature/table (L2 locality)
    const int f = gwarp / CPF;
    const int c = gwarp - f * CPF;
    const int pos = c * CHUNK + lane;          // this lane's value position

    const int myidx = __ldg(values + (size_t)f * NVALS + pos);

    const float4* tab = reinterpret_cast<const float4*>(tables)
                        + (size_t)f * V * (D / 4) + lane;

    const uint32_t sbase =
        (uint32_t)__cvta_generic_to_shared(&sbuf[wib][0][lane]);

    // issue row r's 512B gather into stage r % STAGES (one 16B cp.async/lane)
    auto issue = [&](int r) {
        const int row = __shfl_sync(0xffffffffu, myidx, r);
        const float4* src = tab + (size_t)row * (D / 4);
        const uint32_t dst = sbase + (uint32_t)((r & (STAGES - 1)) * 32) * 16u;
        asm volatile("cp.async.cg.shared.global [%0], [%1], 16;\n\t"
                     "cp.async.commit_group;"
                     :: "r"(dst), "l"(src) : "memory");
    };

    // prologue: fill the ring FIRST; the segment lookup hides under it
    #pragma unroll
    for (int r = 0; r < STAGES; ++r) issue(r);

    // ---- block-cooperative segment lookup ----
    const int* offs = offsets + f * (B + 1);
    const int P0 = ((blockIdx.x * WPB) - f * CPF) * CHUNK;  // block's first position

    if (wib == 0) {
        // s0 = largest j in [0, B-1] with offs[j] <= P0, via 3-level 32-ary
        // warp-parallel search (offs[0]=0 <= P0 always -> ballots nonzero).
        unsigned b1 = __ballot_sync(0xffffffffu, __ldg(offs + lane * 128) <= P0);
        int base1 = (31 - __clz(b1)) * 128;                       // 0..3968
        unsigned b2 = __ballot_sync(0xffffffffu, __ldg(offs + base1 + lane * 4) <= P0);
        int base2 = base1 + (31 - __clz(b2)) * 4;                 // 0..4092
        unsigned b3 = __ballot_sync(0xffffffffu, __ldg(offs + base2 + (lane & 3)) <= P0) & 0xFu;
        if (lane == 0) s_s0 = base2 + (31 - __clz(b3));           // 0..4095
    }
    __syncthreads();
    const int s0 = s_s0;

    // coalesced load of the next 320 boundaries (clamped; offs[B]=N > any pos)
    {
        int j = s0 + 1 + threadIdx.x;
        sb[threadIdx.x] = __ldg(offs + (j > B ? B : j));
    }
    if (threadIdx.x == 0) sb[TPB] = 0x7fffffff;   // sentinel
    __syncthreads();

    // cnt = upper_bound(sb[0..319], pos): first index with sb[idx] > pos.
    // Answers in [0,320] (321 values) -> 9 iterations (2^9=512 >= 321);
    // sentinel keeps post-convergence iterations stable.
    int cnt;
    {
        int lo = 0, hi = TPB;
        #pragma unroll
        for (int it = 0; it < 9; ++it) {
            int mid = (lo + hi) >> 1;
            if (sb[mid] <= pos) lo = mid + 1; else hi = mid;
        }
        cnt = lo;
    }
    int myseg = s0 + cnt;
    if (cnt == TPB) {
        // pathological window (>=320 bags in 320 positions): exact global bsearch
        int lo = 0, hi = B - 1;
        for (int it = 0; it < 12; ++it) {
            int mid = (lo + hi + 1) >> 1;
            if (__ldg(offs + mid) <= pos) lo = mid; else hi = mid - 1;
        }
        myseg = lo;
    }
    // ---- end segment lookup ----

    float4 acc = make_float4(0.f, 0.f, 0.f, 0.f);
    int cur = __shfl_sync(0xffffffffu, myseg, 0);

    auto consume = [&](int j) {
        const float4 v = sbuf[wib][j & (STAGES - 1)][lane];
        const int s = __shfl_sync(0xffffffffu, myseg, j);
        if (s != cur) {                        // warp-uniform branch
            float* o = out + (size_t)cur * (F * D) + f * D + lane * 4;
            asm volatile("red.global.add.v4.f32 [%0], {%1,%2,%3,%4};"
                         :: "l"(o), "f"(acc.x), "f"(acc.y), "f"(acc.z), "f"(acc.w)
                         : "memory");
            acc = make_float4(0.f, 0.f, 0.f, 0.f);
            cur = s;
        }
        acc.x += v.x; acc.y += v.y; acc.z += v.z; acc.w += v.w;
    };

    // steady state: wait oldest, consume, refill
    #pragma unroll
    for (int j = 0; j < CHUNK - STAGES; ++j) {
        cp_wait<STAGES - 1>();
        consume(j);
        issue(j + STAGES);
    }
    // tail: everything issued; drain
    cp_wait<0>();
    #pragma unroll
    for (int j = CHUNK - STAGES; j < CHUNK; ++j) consume(j);

    // final flush
    float* o = out + (size_t)cur * (F * D) + f * D + lane * 4;
    asm volatile("red.global.add.v4.f32 [%0], {%1,%2,%3,%4};"
                 :: "l"(o), "f"(acc.x), "f"(acc.y), "f"(acc.z), "f"(acc.w)
                 : "memory");
}

extern "C" void kernel_launch(void* const* d_in, const int* in_sizes, int n_in,
                              void* d_out, int out_size)
{
    const int*   values  = (const int*)d_in[0];   // [F, NVALS] int32
    const int*   offsets = (const int*)d_in[1];   // [F, B+1] int32
    const float* tables  = (const float*)d_in[2]; // [F, V, D] float32
    float*       out     = (float*)d_out;         // [B, F*D] float32

    // 1) zero the output with a CE memset node (atomics accumulate into it)
    cudaMemsetAsync(out, 0, (size_t)B * F * D * sizeof(float), 0);

    // 2) balanced, smem-pipelined gather + segment-reduce
    const int total_warps = F * CPF;               // 20480
    const int blocks = total_warps / WPB;          // 2048
    ebc_chunk_kernel<<<blocks, TPB>>>(values, offsets, tables, out);
}

// round 16
// speedup vs baseline: 1.2431x; 1.0006x over previous
#include <cuda_runtime.h>
#include <cstdint>

// Problem constants (from reference)
#define F 8
#define B 4096
#define V 100000
#define D 128
#define NVALS 81920
#define CHUNK 32
#define CPF (NVALS / CHUNK)   // 2560 chunks per feature (divisible by WPB)
#define STAGES 8              // per-warp smem pipeline depth (rows in flight)
#define WPB 8                 // warps per block
#define TPB (WPB * 32)        // 256 threads: block covers 256 consecutive positions

template<int N>
__device__ __forceinline__ void cp_wait() {
    asm volatile("cp.async.wait_group %0;" :: "n"(N) : "memory");
}

// One warp per 32-value chunk (perfectly balanced). Row gathers staged through
// a per-warp 8-deep SMEM ring via cp.async. Bag ids computed block-
// cooperatively: warp 0 finds s0 with a 3-level warp-parallel 32-ary search,
// then one coalesced 257-boundary load into smem + per-thread 9-iter LDS
// upper_bound. Segment transitions are precomputed into a single ballot mask
// so the steady-state loop tests an immediate bit instead of issuing a SHFL
// per row (SHFL only on actual transitions, ~1.6/warp). Ring re-issue is
// placed right after the LDS read to shorten the wait->issue recurrence.
// Partial bag sums flushed with red.global.add.v4.f32 (output pre-zeroed by
// the memset node).
__global__ __launch_bounds__(TPB)
void ebc_chunk_kernel(const int* __restrict__ values,    // [F, NVALS]
                      const int* __restrict__ offsets,   // [F, B+1]
                      const float* __restrict__ tables,  // [F, V, D]
                      float* __restrict__ out)           // [B, F*D]
{
    __shared__ float4 sbuf[WPB][STAGES][32];   // 32 KB gather ring
    __shared__ int sb[TPB + 1];                // boundaries offs[s0+1..s0+256] + sentinel
    __shared__ int s_s0;

    const int wib   = threadIdx.x >> 5;
    const int lane  = threadIdx.x & 31;
    const int gwarp = blockIdx.x * WPB + wib;

    // f-major: all warps of a block share one feature/table (L2 locality)
    const int f = gwarp / CPF;
    const int c = gwarp - f * CPF;
    const int pos = c * CHUNK + lane;          // this lane's value position

    const int myidx = __ldg(values + (size_t)f * NVALS + pos);

    const float4* tab = reinterpret_cast<const float4*>(tables)
                        + (size_t)f * V * (D / 4) + lane;

    const uint32_t sbase =
        (uint32_t)__cvta_generic_to_shared(&sbuf[wib][0][lane]);

    // issue row r's 512B gather into stage r % STAGES (one 16B cp.async/lane)
    auto issue = [&](int r) {
        const int row = __shfl_sync(0xffffffffu, myidx, r);
        const float4* src = tab + (size_t)row * (D / 4);
        const uint32_t dst = sbase + (uint32_t)((r & (STAGES - 1)) * 32) * 16u;
        asm volatile("cp.async.cg.shared.global [%0], [%1], 16;\n\t"
                     "cp.async.commit_group;"
                     :: "r"(dst), "l"(src) : "memory");
    };

    // prologue: fill the ring FIRST; the segment lookup hides under it
    #pragma unroll
    for (int r = 0; r < STAGES; ++r) issue(r);

    // ---- block-cooperative segment lookup ----
    const int* offs = offsets + f * (B + 1);
    const int P0 = ((blockIdx.x * WPB) - f * CPF) * CHUNK;  // block's first position

    if (wib == 0) {
        // s0 = largest j in [0, B-1] with offs[j] <= P0, via 3-level 32-ary
        // warp-parallel search (offs[0]=0 <= P0 always -> ballots nonzero).
        unsigned b1 = __ballot_sync(0xffffffffu, __ldg(offs + lane * 128) <= P0);
        int base1 = (31 - __clz(b1)) * 128;                       // 0..3968
        unsigned b2 = __ballot_sync(0xffffffffu, __ldg(offs + base1 + lane * 4) <= P0);
        int base2 = base1 + (31 - __clz(b2)) * 4;                 // 0..4092
        unsigned b3 = __ballot_sync(0xffffffffu, __ldg(offs + base2 + (lane & 3)) <= P0) & 0xFu;
        if (lane == 0) s_s0 = base2 + (31 - __clz(b3));           // 0..4095
    }
    __syncthreads();
    const int s0 = s_s0;

    // coalesced load of the next 256 boundaries (clamped; offs[B]=N > any pos)
    {
        int j = s0 + 1 + threadIdx.x;
        sb[threadIdx.x] = __ldg(offs + (j > B ? B : j));
    }
    if (threadIdx.x == 0) sb[TPB] = 0x7fffffff;   // sentinel
    __syncthreads();

    // cnt = upper_bound(sb[0..255], pos): first index with sb[idx] > pos.
    // Answers in [0,256] (257 values) -> 9 iterations; sentinel keeps
    // post-convergence iterations stable.
    int cnt;
    {
        int lo = 0, hi = TPB;
        #pragma unroll
        for (int it = 0; it < 9; ++it) {
            int mid = (lo + hi) >> 1;
            if (sb[mid] <= pos) lo = mid + 1; else hi = mid;
        }
        cnt = lo;
    }
    int myseg = s0 + cnt;
    if (cnt == TPB) {
        // pathological window (>=256 bags in 256 positions): exact global bsearch
        int lo = 0, hi = B - 1;
        for (int it = 0; it < 12; ++it) {
            int mid = (lo + hi + 1) >> 1;
            if (__ldg(offs + mid) <= pos) lo = mid; else hi = mid - 1;
        }
        myseg = lo;
    }
    // ---- end segment lookup ----

    // Precompute transition mask: bit j set iff seg(pos j) != seg(pos j-1).
    const int segprev = __shfl_up_sync(0xffffffffu, myseg, 1);
    const unsigned tmask =
        __ballot_sync(0xffffffffu, lane > 0 && myseg != segprev);

    float4 acc = make_float4(0.f, 0.f, 0.f, 0.f);
    int cur = __shfl_sync(0xffffffffu, myseg, 0);

    auto flush = [&]() {
        float* o = out + (size_t)cur * (F * D) + f * D + lane * 4;
        asm volatile("red.global.add.v4.f32 [%0], {%1,%2,%3,%4};"
                     :: "l"(o), "f"(acc.x), "f"(acc.y), "f"(acc.z), "f"(acc.w)
                     : "memory");
    };

    auto consume = [&](int j, const float4& v) {
        if (tmask & (1u << j)) {               // warp-uniform immediate test
            flush();
            acc = make_float4(0.f, 0.f, 0.f, 0.f);
            cur = __shfl_sync(0xffffffffu, myseg, j);  // only on transitions
        }
        acc.x += v.x; acc.y += v.y; acc.z += v.z; acc.w += v.w;
    };

    // steady state: wait oldest, read, RE-ISSUE immediately, then accumulate
    #pragma unroll
    for (int j = 0; j < CHUNK - STAGES; ++j) {
        cp_wait<STAGES - 1>();
        const float4 v = sbuf[wib][j & (STAGES - 1)][lane];
        issue(j + STAGES);
        consume(j, v);
    }
    // tail: everything issued; drain
    cp_wait<0>();
    #pragma unroll
    for (int j = CHUNK - STAGES; j < CHUNK; ++j) {
        const float4 v = sbuf[wib][j & (STAGES - 1)][lane];
        consume(j, v);
    }

    // final flush
    flush();
}

extern "C" void kernel_launch(void* const* d_in, const int* in_sizes, int n_in,
                              void* d_out, int out_size)
{
    const int*   values  = (const int*)d_in[0];   // [F, NVALS] int32
    const int*   offsets = (const int*)d_in[1];   // [F, B+1] int32
    const float* tables  = (const float*)d_in[2]; // [F, V, D] float32
    float*       out     = (float*)d_out;         // [B, F*D] float32

    // 1) zero the output with a CE memset node (atomics accumulate into it)
    cudaMemsetAsync(out, 0, (size_t)B * F * D * sizeof(float), 0);

    // 2) balanced, smem-pipelined gather + segment-reduce
    const int total_warps = F * CPF;               // 20480
    const int blocks = total_warps / WPB;          // 2560
    ebc_chunk_kernel<<<blocks, TPB>>>(values, offsets, tables, out);
}